// round 5
// baseline (speedup 1.0000x reference)
#include <cuda_runtime.h>

#define H 512
#define W 512
#define NIMG 48
#define ROWS 8
#define CPT 4                                   // output columns per thread
#define LW (CPT + 2)                            // loaded columns incl. halo = 6
#define STRIPS_X (W / CPT)                      // 128
#define STRIPS_Y (H / ROWS)                     // 64
#define THREADS_PER_IMG (STRIPS_X * STRIPS_Y)   // 8192
#define BLOCK 256

__device__ __forceinline__ float med3f(float a, float b, float c) {
    return fmaxf(fminf(a, b), fminf(fmaxf(a, b), c));
}

// Load row[c0-1 .. c0+4] into d[0..5] with reflect at the image borders.
// c0 is a multiple of 4, so the float4 load is 16B-aligned.
__device__ __forceinline__ void load_row(const float* __restrict__ row, int c0, float* d) {
    const float4 v0 = *reinterpret_cast<const float4*>(row + c0);
    d[1] = v0.x; d[2] = v0.y; d[3] = v0.z; d[4] = v0.w;
    d[0] = row[(c0 == 0) ? 1 : (c0 - 1)];               // reflect col -1 -> 1
    d[5] = row[(c0 + CPT == W) ? (W - 2) : (c0 + CPT)]; // reflect col W -> W-2
}

// Produce output row r for this thread's 4-column strip.
//  pm/pM hold per-column min/max of rows (r-1, r); cur = raw row r.
//  Loads row r+1 into nxt and advances pm/pM to the (r, r+1) pair.
__device__ __forceinline__ void step(const float* __restrict__ base,
                                     float* __restrict__ obase,
                                     int r, int c0,
                                     float* cur, float* nxt,
                                     float* pm, float* pM) {
    int rn = r + 1;
    rn = (rn == H) ? (H - 2) : rn;      // reflect row H -> H-2
    load_row(base + rn * W, c0, nxt);

    float lo[LW], hi[LW], mid[LW];
#pragma unroll
    for (int c = 0; c < LW; ++c) {
        const float n = nxt[c];
        lo[c]  = fminf(pm[c], n);                      // min of column triple
        hi[c]  = fmaxf(pM[c], n);                      // max of column triple
        mid[c] = fmaxf(fminf(pM[c], n), pm[c]);        // mid of column triple
        pm[c]  = fminf(cur[c], n);                     // pair cache for next row
        pM[c]  = fmaxf(cur[c], n);
    }

    float o[CPT];
#pragma unroll
    for (int j = 0; j < CPT; ++j) {
        const float A = fmaxf(fmaxf(lo[j], lo[j + 1]), lo[j + 2]);  // max of mins
        const float C = fminf(fminf(hi[j], hi[j + 1]), hi[j + 2]);  // min of maxes
        const float B = med3f(mid[j], mid[j + 1], mid[j + 2]);      // med of mids
        o[j] = med3f(A, B, C);                                      // exact median9
    }

    *reinterpret_cast<float4*>(obase + r * W + c0) =
        make_float4(o[0], o[1], o[2], o[3]);
}

__global__ __launch_bounds__(BLOCK)
void MedianFilter_22737556865485_kernel(const float* __restrict__ in,
                                        float* __restrict__ out) {
    const int tid = blockIdx.x * BLOCK + threadIdx.x;
    const int img = tid / THREADS_PER_IMG;
    const int s   = tid % THREADS_PER_IMG;
    const int sx  = s % STRIPS_X;
    const int sy  = s / STRIPS_X;
    const int c0  = sx * CPT;
    const int r0  = sy * ROWS;

    const float* base  = in  + (size_t)img * (H * W);
    float*       obase = out + (size_t)img * (H * W);

    float y[LW], z[LW], pm[LW], pM[LW];

    // Prologue: pair (r0-1, r0); reflect row -1 -> 1.
    {
        float t[LW];
        const int rm = (r0 == 0) ? 1 : (r0 - 1);
        load_row(base + rm * W, c0, t);
        load_row(base + r0 * W, c0, y);
#pragma unroll
        for (int c = 0; c < LW; ++c) {
            pm[c] = fminf(t[c], y[c]);
            pM[c] = fmaxf(t[c], y[c]);
        }
    }

    // Period-2 register rotation: y and z alternate roles, no copies.
#pragma unroll 1
    for (int i = 0; i < ROWS; i += 2) {
        step(base, obase, r0 + i,     c0, y, z, pm, pM);
        step(base, obase, r0 + i + 1, c0, z, y, pm, pM);
    }
}

extern "C" void kernel_launch(void* const* d_in, const int* in_sizes, int n_in,
                              void* d_out, int out_size) {
    const float* in  = (const float*)d_in[0];
    float*       out = (float*)d_out;
    const int total_threads = NIMG * THREADS_PER_IMG;   // 393216
    MedianFilter_22737556865485_kernel<<<total_threads / BLOCK, BLOCK>>>(in, out);
}

// round 6
// speedup vs baseline: 1.1364x; 1.1364x over previous
#include <cuda_runtime.h>

#define H 512
#define W 512
#define NIMG 48
#define ROWS 8
#define CPT 8                                   // output columns per thread
#define LW (CPT + 2)                            // loaded columns incl. halo = 10
#define STRIPS_X (W / CPT)                      // 64
#define STRIPS_Y (H / ROWS)                     // 64
#define THREADS_PER_IMG (STRIPS_X * STRIPS_Y)   // 4096
#define BLOCK 128

__device__ __forceinline__ float med3f(float a, float b, float c) {
    return fmaxf(fminf(a, b), fminf(fmaxf(a, b), c));
}

// Load row[c0-1 .. c0+8] into d[0..9] with reflect at the image borders.
// c0 is a multiple of 8, so the two float4 loads are 32B-aligned.
__device__ __forceinline__ void load_row(const float* __restrict__ row, int c0, float* d) {
    const float4 v0 = *reinterpret_cast<const float4*>(row + c0);
    const float4 v1 = *reinterpret_cast<const float4*>(row + c0 + 4);
    d[1] = v0.x; d[2] = v0.y; d[3] = v0.z; d[4] = v0.w;
    d[5] = v1.x; d[6] = v1.y; d[7] = v1.z; d[8] = v1.w;
    d[0] = row[(c0 == 0) ? 1 : (c0 - 1)];               // reflect col -1 -> 1
    d[9] = row[(c0 + CPT == W) ? (W - 2) : (c0 + CPT)]; // reflect col W -> W-2
}

__global__ __launch_bounds__(BLOCK)
void MedianFilter_22737556865485_kernel(const float* __restrict__ in,
                                        float* __restrict__ out) {
    const int tid = blockIdx.x * BLOCK + threadIdx.x;
    const int img = tid / THREADS_PER_IMG;
    const int s   = tid % THREADS_PER_IMG;
    const int sx  = s % STRIPS_X;
    const int sy  = s / STRIPS_X;
    const int c0  = sx * CPT;
    const int r0  = sy * ROWS;

    const float* base  = in  + (size_t)img * (H * W);
    float*       obase = out + (size_t)img * (H * W);

    // Triple-buffered row registers + running (prev,cur) min/max pair cache.
    float buf[3][LW], pm[LW], pM[LW];

    // Prologue: rows r0-1 (reflect -1 -> 1), r0, and r0+1 resident.
    {
        float t[LW];
        const int rm = (r0 == 0) ? 1 : (r0 - 1);
        load_row(base + rm * W, c0, t);
        load_row(base + r0 * W, c0, buf[0]);
#pragma unroll
        for (int c = 0; c < LW; ++c) {
            pm[c] = fminf(t[c], buf[0][c]);
            pM[c] = fmaxf(t[c], buf[0][c]);
        }
        load_row(base + (r0 + 1) * W, c0, buf[1]);   // nxt for first step
    }

    // Fully unrolled, software-pipelined: prefetch row r+2 before computing
    // output row r from the already-loaded row r+1.
#pragma unroll
    for (int i = 0; i < ROWS; ++i) {
        const float* cur = buf[i % 3];           // row r0+i   (raw)
        const float* nxt = buf[(i + 1) % 3];     // row r0+i+1 (raw, resident)
        float*       pf  = buf[(i + 2) % 3];     // row r0+i+2 (prefetch target)

        if (i < ROWS - 1) {                      // compile-time; last step needs no prefetch
            int rp = r0 + i + 2;
            rp = (rp == H) ? (H - 2) : rp;       // reflect row H -> H-2
            load_row(base + rp * W, c0, pf);     // issued ~160 instrs before its use
        }

        float lo[LW], hi[LW], mid[LW];
#pragma unroll
        for (int c = 0; c < LW; ++c) {
            const float n = nxt[c];
            lo[c]  = fminf(pm[c], n);                  // min of column triple
            hi[c]  = fmaxf(pM[c], n);                  // max of column triple
            mid[c] = fmaxf(fminf(pM[c], n), pm[c]);    // mid of column triple
            pm[c]  = fminf(cur[c], n);                 // pair cache -> (r, r+1)
            pM[c]  = fmaxf(cur[c], n);
        }

        float o[CPT];
#pragma unroll
        for (int j = 0; j < CPT; ++j) {
            const float A = fmaxf(fmaxf(lo[j], lo[j + 1]), lo[j + 2]);  // max of mins
            const float C = fminf(fminf(hi[j], hi[j + 1]), hi[j + 2]);  // min of maxes
            const float B = med3f(mid[j], mid[j + 1], mid[j + 2]);      // med of mids
            o[j] = med3f(A, B, C);                                      // exact median9
        }

        float* orow = obase + (r0 + i) * W + c0;
        *reinterpret_cast<float4*>(orow)     = make_float4(o[0], o[1], o[2], o[3]);
        *reinterpret_cast<float4*>(orow + 4) = make_float4(o[4], o[5], o[6], o[7]);
    }
}

extern "C" void kernel_launch(void* const* d_in, const int* in_sizes, int n_in,
                              void* d_out, int out_size) {
    const float* in  = (const float*)d_in[0];
    float*       out = (float*)d_out;
    const int total_threads = NIMG * THREADS_PER_IMG;   // 196608
    MedianFilter_22737556865485_kernel<<<total_threads / BLOCK, BLOCK>>>(in, out);
}

// round 7
// speedup vs baseline: 1.1792x; 1.0377x over previous
#include <cuda_runtime.h>

#define H 512
#define W 512
#define NIMG 48
#define ROWS 4
#define CPT 8                                   // output columns per thread
#define STRIPS_X (W / CPT)                      // 64
#define STRIPS_Y (H / ROWS)                     // 128
#define THREADS_PER_IMG (STRIPS_X * STRIPS_Y)   // 8192
#define BLOCK 128

__device__ __forceinline__ float med3f(float a, float b, float c) {
    return fmaxf(fminf(a, b), fminf(fmaxf(a, b), c));
}

// Vector part of a row load: cols [c0, c0+8) into d[1..8] (two aligned float4s).
// d[0] receives the warp-edge scalar (only the 2 edge lanes that need one load it).
__device__ __forceinline__ void load_rowv(const float* __restrict__ row, int c0,
                                          bool has_e, int eoff, float* d) {
    const float4 v0 = *reinterpret_cast<const float4*>(row + c0);
    const float4 v1 = *reinterpret_cast<const float4*>(row + c0 + 4);
    d[1] = v0.x; d[2] = v0.y; d[3] = v0.z; d[4] = v0.w;
    d[5] = v1.x; d[6] = v1.y; d[7] = v1.z; d[8] = v1.w;
    d[0] = has_e ? row[eoff] : 0.0f;            // predicated 1-lane LDG
}

// Materialize halo cols into d[0]/d[9] via intra-warp shuffles.
// Interior lanes get neighbors' edge elements; warp-edge lanes use the
// predicated scalar (in d[0]) or in-register reflection at image borders.
__device__ __forceinline__ void expand(float* d, int lane, int c0) {
    float l = __shfl_up_sync(0xffffffffu, d[8], 1);    // neighbor col c0-1
    float r = __shfl_down_sync(0xffffffffu, d[1], 1);  // neighbor col c0+8
    if (lane == 0)  l = (c0 == 0)       ? d[2] : d[0]; // reflect col -1 -> 1
    if (lane == 31) r = (c0 + CPT == W) ? d[7] : d[0]; // reflect col W -> W-2
    d[0] = l; d[9] = r;
}

__global__ __launch_bounds__(BLOCK)
void MedianFilter_22737556865485_kernel(const float* __restrict__ in,
                                        float* __restrict__ out) {
    const int tid  = blockIdx.x * BLOCK + threadIdx.x;
    const int lane = threadIdx.x & 31;
    const int img  = tid / THREADS_PER_IMG;
    const int s    = tid % THREADS_PER_IMG;
    const int sx   = s % STRIPS_X;               // lane == sx % 32 (warp-coherent)
    const int sy   = s / STRIPS_X;
    const int c0   = sx * CPT;
    const int r0   = sy * ROWS;

    // Per-thread warp-edge scalar descriptor (loop-invariant).
    bool has_e = false; int eoff = 0;
    if (lane == 0  && c0 != 0)       { has_e = true; eoff = c0 - 1; }
    if (lane == 31 && c0 + CPT != W) { has_e = true; eoff = c0 + CPT; }

    const float* base  = in  + (size_t)img * (H * W);
    float*       obase = out + (size_t)img * (H * W);

    float buf[3][10], pm[10], pM[10];

    // Prologue: rows r0-1 (reflect -1 -> 1), r0 expanded + paired; r0+1 loaded.
    {
        float t[10];
        const int rm = (r0 == 0) ? 1 : (r0 - 1);
        load_rowv(base + rm * W, c0, has_e, eoff, t);
        load_rowv(base + r0 * W, c0, has_e, eoff, buf[0]);
        expand(t, lane, c0);
        expand(buf[0], lane, c0);
#pragma unroll
        for (int c = 0; c < 10; ++c) {
            pm[c] = fminf(t[c], buf[0][c]);
            pM[c] = fmaxf(t[c], buf[0][c]);
        }
        load_rowv(base + (r0 + 1) * W, c0, has_e, eoff, buf[1]);
    }

    // Software-pipelined, fully unrolled: prefetch row r+2, then consume row
    // r+1 (expand halo via shuffle now that its loads have had a full
    // iteration of cover) to emit output row r.
#pragma unroll
    for (int i = 0; i < ROWS; ++i) {
        const float* cur = buf[i % 3];           // row r0+i   (expanded)
        float*       nxt = buf[(i + 1) % 3];     // row r0+i+1 (loaded, raw)
        float*       pf  = buf[(i + 2) % 3];     // row r0+i+2 (prefetch target)

        if (i < ROWS - 1) {
            int rp = r0 + i + 2;
            rp = (rp == H) ? (H - 2) : rp;       // reflect row H -> H-2
            load_rowv(base + rp * W, c0, has_e, eoff, pf);
        }

        expand(nxt, lane, c0);

        float lo[10], hi[10], mid[10];
#pragma unroll
        for (int c = 0; c < 10; ++c) {
            const float n = nxt[c];
            lo[c]  = fminf(pm[c], n);                  // min of column triple
            hi[c]  = fmaxf(pM[c], n);                  // max of column triple
            mid[c] = fmaxf(fminf(pM[c], n), pm[c]);    // mid of column triple
            pm[c]  = fminf(cur[c], n);                 // pair cache -> (r, r+1)
            pM[c]  = fmaxf(cur[c], n);
        }

        float o[CPT];
#pragma unroll
        for (int j = 0; j < CPT; ++j) {
            const float A = fmaxf(fmaxf(lo[j], lo[j + 1]), lo[j + 2]);  // max of mins
            const float C = fminf(fminf(hi[j], hi[j + 1]), hi[j + 2]);  // min of maxes
            const float B = med3f(mid[j], mid[j + 1], mid[j + 2]);      // med of mids
            o[j] = med3f(A, B, C);                                      // exact median9
        }

        float* orow = obase + (r0 + i) * W + c0;
        *reinterpret_cast<float4*>(orow)     = make_float4(o[0], o[1], o[2], o[3]);
        *reinterpret_cast<float4*>(orow + 4) = make_float4(o[4], o[5], o[6], o[7]);
    }
}

extern "C" void kernel_launch(void* const* d_in, const int* in_sizes, int n_in,
                              void* d_out, int out_size) {
    const float* in  = (const float*)d_in[0];
    float*       out = (float*)d_out;
    const int total_threads = NIMG * THREADS_PER_IMG;   // 393216
    MedianFilter_22737556865485_kernel<<<total_threads / BLOCK, BLOCK>>>(in, out);
}